// round 1
// baseline (speedup 1.0000x reference)
#include <cuda_runtime.h>
#include <mma.h>

using namespace nvcuda;

static constexpr int NP   = 100000;   // points
static constexpr int NPAD = 100032;   // padded to multiple of 64
static constexpr int CH   = 128;
static constexpr int HH   = 64;

// Scratch (device globals; no allocations allowed)
__device__ float g_y [(size_t)NPAD * CH];   // y = x@w1 + b1
__device__ float g_r1[(size_t)NPAD * HH];   // relu(sconv1)
__device__ float g_r2[(size_t)NPAD * HH];   // relu(sconv2)

__device__ __forceinline__ float4 to_tf32_4(float4 v) {
    v.x = wmma::__float_to_tf32(v.x);
    v.y = wmma::__float_to_tf32(v.y);
    v.z = wmma::__float_to_tf32(v.z);
    v.w = wmma::__float_to_tf32(v.w);
    return v;
}

// ---------------------------------------------------------------------------
// GEMM1: g_y[n, 0:128] = x[n, :] @ w1 + b1
// Block: 256 thr (8 warps, 4x2), tile 64 rows x 128 cols, K=128.
// ---------------------------------------------------------------------------
__global__ __launch_bounds__(256) void gemm1_kernel(
    const float* __restrict__ x,
    const float* __restrict__ w1,
    const float* __restrict__ b1)
{
    extern __shared__ float smem[];
    float* As = smem;               // 64 x 132
    float* Bs = smem + 64 * 132;    // 128 x 132

    const int tid = threadIdx.x;
    const int rowBase = blockIdx.x * 64;

    // Fill A (x tile), zero-pad rows >= NP
    for (int j = tid; j < 64 * 32; j += 256) {
        int row = j >> 5, seg = j & 31;
        int n = rowBase + row;
        float4 v = make_float4(0.f, 0.f, 0.f, 0.f);
        if (n < NP) v = to_tf32_4(*(const float4*)(x + (size_t)n * 128 + seg * 4));
        *(float4*)(As + row * 132 + seg * 4) = v;
    }
    // Fill B (full w1: 128x128)
    for (int j = tid; j < 128 * 32; j += 256) {
        int row = j >> 5, seg = j & 31;
        float4 v = to_tf32_4(*(const float4*)(w1 + row * 128 + seg * 4));
        *(float4*)(Bs + row * 132 + seg * 4) = v;
    }
    __syncthreads();

    const int warp = tid >> 5;
    const int mw = warp >> 1;   // 0..3 (16 rows each)
    const int nw = warp & 1;    // 0..1 (64 cols each)

    wmma::fragment<wmma::accumulator, 16, 16, 8, float> c[4];
    #pragma unroll
    for (int f = 0; f < 4; f++) wmma::fill_fragment(c[f], 0.f);

    #pragma unroll
    for (int kk = 0; kk < 16; kk++) {
        wmma::fragment<wmma::matrix_a, 16, 16, 8, wmma::precision::tf32, wmma::row_major> a;
        wmma::load_matrix_sync(a, As + (mw * 16) * 132 + kk * 8, 132);
        #pragma unroll
        for (int f = 0; f < 4; f++) {
            wmma::fragment<wmma::matrix_b, 16, 16, 8, wmma::precision::tf32, wmma::row_major> b;
            wmma::load_matrix_sync(b, Bs + (kk * 8) * 132 + nw * 64 + f * 16, 132);
            wmma::mma_sync(c[f], a, b, c[f]);
        }
    }
    __syncthreads();   // everyone done reading As/Bs

    // Stage results into As region (64 x 132)
    #pragma unroll
    for (int f = 0; f < 4; f++)
        wmma::store_matrix_sync(As + (mw * 16) * 132 + nw * 64 + f * 16, c[f], 132,
                                wmma::mem_row_major);
    __syncthreads();

    // Epilogue: + b1, write g_y (padded, no row guard needed)
    for (int j = tid; j < 64 * 32; j += 256) {
        int row = j >> 5, seg = j & 31;
        int n = rowBase + row;
        float4 v  = *(float4*)(As + row * 132 + seg * 4);
        float4 bb = *(const float4*)(b1 + seg * 4);
        v.x += bb.x; v.y += bb.y; v.z += bb.z; v.w += bb.w;
        *(float4*)(g_y + (size_t)n * 128 + seg * 4) = v;
    }
}

// ---------------------------------------------------------------------------
// sconv: out[n, 0:64] = relu( sum_k gathered(feat)[nbr[k,n]] @ rw[k] + rb )
// SRC=0: feat = g_y (row stride 128, first 64 cols), out = g_r1
// SRC=1: feat = g_r1 (row stride 64), out = g_r2
// Block: 128 thr (4 warps), tile 64 rows x 64 cols; loop over 27 offsets.
// ---------------------------------------------------------------------------
template <int SRC>
__global__ __launch_bounds__(128) void sconv_kernel(
    const int*   __restrict__ nbr,
    const float* __restrict__ rw,
    const float* __restrict__ rb)
{
    __shared__ alignas(16) float As[64 * 68];   // gathered features
    __shared__ alignas(16) float Bs[64 * 68];   // rw[k]

    const float* feat = (SRC == 0) ? g_y : g_r1;
    float*       outp = (SRC == 0) ? g_r1 : g_r2;
    const int    ld4  = (SRC == 0) ? 32 : 16;   // feature row stride in float4

    const int tid = threadIdx.x;
    const int rowBase = blockIdx.x * 64;
    const int warp = tid >> 5;   // 0..3, 16 rows each

    wmma::fragment<wmma::accumulator, 16, 16, 8, float> c[4];
    #pragma unroll
    for (int f = 0; f < 4; f++) wmma::fill_fragment(c[f], 0.f);

    for (int kk = 0; kk < 27; kk++) {
        __syncthreads();   // previous iteration's MMAs finished reading As/Bs

        // Fill Bs = rw[kk] (64x64)
        for (int j = tid; j < 64 * 16; j += 128) {
            *(float4*)(Bs + (j >> 4) * 68 + (j & 15) * 4) =
                to_tf32_4(*(const float4*)(rw + (size_t)kk * 4096 + j * 4));
        }
        // Gather As (masked neighbor rows)
        for (int j = tid; j < 64 * 16; j += 128) {
            int row = j >> 4, seg = j & 15;
            int n = rowBase + row;
            int idx = (n < NP) ? __ldg(nbr + (size_t)kk * NP + n) : -1;
            float4 v = make_float4(0.f, 0.f, 0.f, 0.f);
            if (idx >= 0)
                v = to_tf32_4(*(const float4*)(feat + (size_t)idx * (ld4 * 4) + seg * 4));
            *(float4*)(As + row * 68 + seg * 4) = v;
        }
        __syncthreads();

        #pragma unroll
        for (int k8 = 0; k8 < 8; k8++) {
            wmma::fragment<wmma::matrix_a, 16, 16, 8, wmma::precision::tf32, wmma::row_major> a;
            wmma::load_matrix_sync(a, As + (warp * 16) * 68 + k8 * 8, 68);
            #pragma unroll
            for (int f = 0; f < 4; f++) {
                wmma::fragment<wmma::matrix_b, 16, 16, 8, wmma::precision::tf32, wmma::row_major> b;
                wmma::load_matrix_sync(b, Bs + (k8 * 8) * 68 + f * 16, 68);
                wmma::mma_sync(c[f], a, b, c[f]);
            }
        }
    }
    __syncthreads();

    // Stage into As and apply bias + relu
    #pragma unroll
    for (int f = 0; f < 4; f++)
        wmma::store_matrix_sync(As + (warp * 16) * 68 + f * 16, c[f], 68, wmma::mem_row_major);
    __syncthreads();

    for (int j = tid; j < 64 * 16; j += 128) {
        int row = j >> 4, seg = j & 15;
        float4 v  = *(float4*)(As + row * 68 + seg * 4);
        float4 bb = *(const float4*)(rb + seg * 4);
        v.x = fmaxf(v.x + bb.x, 0.f);
        v.y = fmaxf(v.y + bb.y, 0.f);
        v.z = fmaxf(v.z + bb.z, 0.f);
        v.w = fmaxf(v.w + bb.w, 0.f);
        *(float4*)(outp + (size_t)(rowBase + row) * 64 + seg * 4) = v;
    }
}

// ---------------------------------------------------------------------------
// GEMM2: out[n,:] = x[n,:] + concat(g_r2[n]+2*g_y[n,0:64], g_y[n,64:128]) @ w2 + b2
// ---------------------------------------------------------------------------
__global__ __launch_bounds__(256) void gemm2_kernel(
    const float* __restrict__ x,
    const float* __restrict__ w2,
    const float* __restrict__ b2,
    float* __restrict__ out)
{
    extern __shared__ float smem[];
    float* As = smem;               // 64 x 132
    float* Bs = smem + 64 * 132;    // 128 x 132

    const int tid = threadIdx.x;
    const int rowBase = blockIdx.x * 64;

    // Build A = concat(r2 + 2*conv_x, trans_x)
    for (int j = tid; j < 64 * 32; j += 256) {
        int row = j >> 5, seg = j & 31;
        int n = rowBase + row;     // always < NPAD, scratch is padded
        float4 v;
        if (seg < 16) {
            float4 r = *(const float4*)(g_r2 + (size_t)n * 64  + seg * 4);
            float4 y = *(const float4*)(g_y  + (size_t)n * 128 + seg * 4);
            v.x = r.x + 2.f * y.x;
            v.y = r.y + 2.f * y.y;
            v.z = r.z + 2.f * y.z;
            v.w = r.w + 2.f * y.w;
        } else {
            v = *(const float4*)(g_y + (size_t)n * 128 + seg * 4);
        }
        *(float4*)(As + row * 132 + seg * 4) = to_tf32_4(v);
    }
    for (int j = tid; j < 128 * 32; j += 256) {
        int row = j >> 5, seg = j & 31;
        float4 v = to_tf32_4(*(const float4*)(w2 + row * 128 + seg * 4));
        *(float4*)(Bs + row * 132 + seg * 4) = v;
    }
    __syncthreads();

    const int warp = tid >> 5;
    const int mw = warp >> 1, nw = warp & 1;

    wmma::fragment<wmma::accumulator, 16, 16, 8, float> c[4];
    #pragma unroll
    for (int f = 0; f < 4; f++) wmma::fill_fragment(c[f], 0.f);

    #pragma unroll
    for (int kk = 0; kk < 16; kk++) {
        wmma::fragment<wmma::matrix_a, 16, 16, 8, wmma::precision::tf32, wmma::row_major> a;
        wmma::load_matrix_sync(a, As + (mw * 16) * 132 + kk * 8, 132);
        #pragma unroll
        for (int f = 0; f < 4; f++) {
            wmma::fragment<wmma::matrix_b, 16, 16, 8, wmma::precision::tf32, wmma::row_major> b;
            wmma::load_matrix_sync(b, Bs + (kk * 8) * 132 + nw * 64 + f * 16, 132);
            wmma::mma_sync(c[f], a, b, c[f]);
        }
    }
    __syncthreads();

    #pragma unroll
    for (int f = 0; f < 4; f++)
        wmma::store_matrix_sync(As + (mw * 16) * 132 + nw * 64 + f * 16, c[f], 132,
                                wmma::mem_row_major);
    __syncthreads();

    // Epilogue: + b2 + x residual, guarded write to exact-size out buffer
    for (int j = tid; j < 64 * 32; j += 256) {
        int row = j >> 5, seg = j & 31;
        int n = rowBase + row;
        if (n < NP) {
            float4 v  = *(float4*)(As + row * 132 + seg * 4);
            float4 bb = *(const float4*)(b2 + seg * 4);
            float4 xr = *(const float4*)(x + (size_t)n * 128 + seg * 4);
            v.x += bb.x + xr.x;
            v.y += bb.y + xr.y;
            v.z += bb.z + xr.z;
            v.w += bb.w + xr.w;
            *(float4*)(out + (size_t)n * 128 + seg * 4) = v;
        }
    }
}

// ---------------------------------------------------------------------------
extern "C" void kernel_launch(void* const* d_in, const int* in_sizes, int n_in,
                              void* d_out, int out_size)
{
    const float* x   = (const float*)d_in[0];
    const float* w1  = (const float*)d_in[1];
    const float* b1  = (const float*)d_in[2];
    const float* w2  = (const float*)d_in[3];
    const float* b2  = (const float*)d_in[4];
    const float* rw1 = (const float*)d_in[5];
    const float* rb1 = (const float*)d_in[6];
    const float* rw2 = (const float*)d_in[7];
    const float* rb2 = (const float*)d_in[8];
    const int*   nbr = (const int*)  d_in[9];
    float* out = (float*)d_out;

    const int SMEM_G = (64 + 128) * 132 * (int)sizeof(float);   // ~101 KB
    cudaFuncSetAttribute(gemm1_kernel, cudaFuncAttributeMaxDynamicSharedMemorySize, SMEM_G);
    cudaFuncSetAttribute(gemm2_kernel, cudaFuncAttributeMaxDynamicSharedMemorySize, SMEM_G);

    const int grid = NPAD / 64;   // 1563

    gemm1_kernel<<<grid, 256, SMEM_G>>>(x, w1, b1);
    sconv_kernel<0><<<grid, 128>>>(nbr, rw1, rb1);
    sconv_kernel<1><<<grid, 128>>>(nbr, rw2, rb2);
    gemm2_kernel<<<grid, 256, SMEM_G>>>(x, w2, b2, out);
}

// round 2
// speedup vs baseline: 1.0569x; 1.0569x over previous
#include <cuda_runtime.h>
#include <mma.h>

using namespace nvcuda;

static constexpr int NP   = 100000;   // points
static constexpr int NPAD = 100096;   // padded to multiple of 128
static constexpr int CH   = 128;
static constexpr int HH   = 64;

// Scratch (device globals; no allocations allowed)
__device__ float g_y [(size_t)NPAD * CH];   // y = x@w1 + b1
__device__ float g_r1[(size_t)NPAD * HH];   // relu(sconv1)
__device__ float g_r2[(size_t)NPAD * HH];   // relu(sconv2)

// ---------------------------------------------------------------------------
// cp.async helpers (16B, zero-fill variant for masked gathers)
// ---------------------------------------------------------------------------
__device__ __forceinline__ unsigned smem_u32(const void* p) {
    return (unsigned)__cvta_generic_to_shared(p);
}
__device__ __forceinline__ void cp16(unsigned dst, const void* src, int src_size) {
    asm volatile("cp.async.cg.shared.global [%0], [%1], 16, %2;"
                 :: "r"(dst), "l"(src), "r"(src_size));
}
__device__ __forceinline__ void cp_commit() {
    asm volatile("cp.async.commit_group;");
}
template <int N>
__device__ __forceinline__ void cp_wait() {
    asm volatile("cp.async.wait_group %0;" :: "n"(N));
}

// ---------------------------------------------------------------------------
// GEMM1: g_y[n, 0:128] = x[n, :] @ w1 + b1
// Block: 256 thr (8 warps, 4x2), tile 64 rows x 128 cols, K=128.
// Fills via cp.async (tf32 truncation at MMA).
// ---------------------------------------------------------------------------
__global__ __launch_bounds__(256) void gemm1_kernel(
    const float* __restrict__ x,
    const float* __restrict__ w1,
    const float* __restrict__ b1)
{
    extern __shared__ float smem[];
    float* As = smem;               // 64 x 132
    float* Bs = smem + 64 * 132;    // 128 x 132

    const int tid = threadIdx.x;
    const int rowBase = blockIdx.x * 64;

    // A tile (x), zero-fill padded rows
    #pragma unroll
    for (int i = 0; i < 8; i++) {
        int j = tid + i * 256;                 // 0..2047
        int row = j >> 5, seg = j & 31;
        int n = rowBase + row;
        cp16(smem_u32(As + row * 132 + seg * 4),
             x + (size_t)n * 128 + seg * 4,
             (n < NP) ? 16 : 0);
    }
    // B tile (full w1)
    #pragma unroll
    for (int i = 0; i < 16; i++) {
        int j = tid + i * 256;                 // 0..4095
        int row = j >> 5, seg = j & 31;
        cp16(smem_u32(Bs + row * 132 + seg * 4), w1 + j * 4, 16);
    }
    cp_commit();
    cp_wait<0>();
    __syncthreads();

    const int warp = tid >> 5;
    const int mw = warp >> 1;   // 0..3 (16 rows each)
    const int nw = warp & 1;    // 0..1 (64 cols each)

    wmma::fragment<wmma::accumulator, 16, 16, 8, float> c[4];
    #pragma unroll
    for (int f = 0; f < 4; f++) wmma::fill_fragment(c[f], 0.f);

    #pragma unroll
    for (int kk = 0; kk < 16; kk++) {
        wmma::fragment<wmma::matrix_a, 16, 16, 8, wmma::precision::tf32, wmma::row_major> a;
        wmma::load_matrix_sync(a, As + (mw * 16) * 132 + kk * 8, 132);
        #pragma unroll
        for (int f = 0; f < 4; f++) {
            wmma::fragment<wmma::matrix_b, 16, 16, 8, wmma::precision::tf32, wmma::row_major> b;
            wmma::load_matrix_sync(b, Bs + (kk * 8) * 132 + nw * 64 + f * 16, 132);
            wmma::mma_sync(c[f], a, b, c[f]);
        }
    }
    __syncthreads();

    #pragma unroll
    for (int f = 0; f < 4; f++)
        wmma::store_matrix_sync(As + (mw * 16) * 132 + nw * 64 + f * 16, c[f], 132,
                                wmma::mem_row_major);
    __syncthreads();

    #pragma unroll
    for (int i = 0; i < 8; i++) {
        int j = tid + i * 256;
        int row = j >> 5, seg = j & 31;
        int n = rowBase + row;
        float4 v  = *(float4*)(As + row * 132 + seg * 4);
        float4 bb = *(const float4*)(b1 + seg * 4);
        v.x += bb.x; v.y += bb.y; v.z += bb.z; v.w += bb.w;
        *(float4*)(g_y + (size_t)n * 128 + seg * 4) = v;
    }
}

// ---------------------------------------------------------------------------
// sconv: out[n, 0:64] = relu( sum_k gathered(feat)[nbr[k,n]] @ rw[k] + rb )
// 256 thr (8 warps), tile 128 rows x 64 cols, double-buffered cp.async pipeline
// over the 27 offsets. Masked rows use cp.async zero-fill (src-size 0).
// ---------------------------------------------------------------------------
template <int SRC>
__global__ __launch_bounds__(256) void sconv_kernel(
    const int*   __restrict__ nbr,
    const float* __restrict__ rw,
    const float* __restrict__ rb)
{
    extern __shared__ float smem[];
    float* As = smem;                   // 2 x 128 x 68
    float* Bs = smem + 2 * 128 * 68;    // 2 x 64 x 68

    const float* feat = (SRC == 0) ? g_y : g_r1;
    float*       outp = (SRC == 0) ? g_r1 : g_r2;
    const int    ldf  = (SRC == 0) ? 128 : 64;   // feature row stride (floats)

    const int tid = threadIdx.x;
    const int rowBase = blockIdx.x * 128;
    const int warp = tid >> 5;          // 0..7, 16 rows each

    // per-thread gather assignment: 2 threads per row, 8 x 16B each
    const int arow  = tid >> 1;         // 0..127
    const int ahalf = tid & 1;          // 0..1  (32 floats each)
    const int an    = rowBase + arow;

    auto prefetch = [&](int kk, int buf) {
        // weights 64x64
        const float* wsrc = rw + (size_t)kk * 4096;
        float* bdst = Bs + buf * 64 * 68;
        #pragma unroll
        for (int i = 0; i < 4; i++) {
            int j = tid + i * 256;      // 0..1023
            int row = j >> 4, seg = j & 15;
            cp16(smem_u32(bdst + row * 68 + seg * 4), wsrc + j * 4, 16);
        }
        // gathered features 128x64
        int idx = (an < NP) ? __ldg(nbr + (size_t)kk * NP + an) : -1;
        int sz  = (idx >= 0) ? 16 : 0;
        const float* src = feat + (size_t)(idx < 0 ? 0 : idx) * ldf + ahalf * 32;
        float* adst = As + buf * 128 * 68 + arow * 68 + ahalf * 32;
        #pragma unroll
        for (int s = 0; s < 8; s++)
            cp16(smem_u32(adst + s * 4), src + s * 4, sz);
    };

    wmma::fragment<wmma::accumulator, 16, 16, 8, float> c[4];
    #pragma unroll
    for (int f = 0; f < 4; f++) wmma::fill_fragment(c[f], 0.f);

    prefetch(0, 0);
    cp_commit();

    for (int kk = 0; kk < 27; kk++) {
        const int buf = kk & 1;
        if (kk + 1 < 27) {
            prefetch(kk + 1, buf ^ 1);
            cp_commit();
            cp_wait<1>();               // stage kk complete
        } else {
            cp_wait<0>();
        }
        __syncthreads();                // stage kk visible to all

        const float* a0 = As + buf * 128 * 68 + (warp * 16) * 68;
        const float* b0 = Bs + buf * 64 * 68;
        #pragma unroll
        for (int k8 = 0; k8 < 8; k8++) {
            wmma::fragment<wmma::matrix_a, 16, 16, 8, wmma::precision::tf32, wmma::row_major> a;
            wmma::load_matrix_sync(a, a0 + k8 * 8, 68);
            #pragma unroll
            for (int f = 0; f < 4; f++) {
                wmma::fragment<wmma::matrix_b, 16, 16, 8, wmma::precision::tf32, wmma::row_major> b;
                wmma::load_matrix_sync(b, b0 + (k8 * 8) * 68 + f * 16, 68);
                wmma::mma_sync(c[f], a, b, c[f]);
            }
        }
        __syncthreads();                // done reading buf before it is refilled
    }

    // epilogue: stage into As, bias + relu, write
    #pragma unroll
    for (int f = 0; f < 4; f++)
        wmma::store_matrix_sync(As + (warp * 16) * 68 + f * 16, c[f], 68, wmma::mem_row_major);
    __syncthreads();

    #pragma unroll
    for (int i = 0; i < 8; i++) {
        int j = tid + i * 256;          // 0..2047
        int row = j >> 4, seg = j & 15;
        float4 v  = *(float4*)(As + row * 68 + seg * 4);
        float4 bb = *(const float4*)(rb + seg * 4);
        v.x = fmaxf(v.x + bb.x, 0.f);
        v.y = fmaxf(v.y + bb.y, 0.f);
        v.z = fmaxf(v.z + bb.z, 0.f);
        v.w = fmaxf(v.w + bb.w, 0.f);
        *(float4*)(outp + (size_t)(rowBase + row) * 64 + seg * 4) = v;
    }
}

// ---------------------------------------------------------------------------
// GEMM2: out[n,:] = x[n,:] + concat(g_r2[n]+2*g_y[n,0:64], g_y[n,64:128]) @ w2 + b2
// ---------------------------------------------------------------------------
__global__ __launch_bounds__(256) void gemm2_kernel(
    const float* __restrict__ x,
    const float* __restrict__ w2,
    const float* __restrict__ b2,
    float* __restrict__ out)
{
    extern __shared__ float smem[];
    float* As = smem;               // 64 x 132
    float* Bs = smem + 64 * 132;    // 128 x 132

    const int tid = threadIdx.x;
    const int rowBase = blockIdx.x * 64;

    // start weight loads first (async)
    #pragma unroll
    for (int i = 0; i < 16; i++) {
        int j = tid + i * 256;
        int row = j >> 5, seg = j & 31;
        cp16(smem_u32(Bs + row * 132 + seg * 4), w2 + j * 4, 16);
    }
    cp_commit();

    // build A = concat(r2 + 2*conv_x, trans_x) in registers (scratch is padded)
    #pragma unroll
    for (int i = 0; i < 8; i++) {
        int j = tid + i * 256;
        int row = j >> 5, seg = j & 31;
        int n = rowBase + row;
        float4 v;
        if (seg < 16) {
            float4 r = *(const float4*)(g_r2 + (size_t)n * 64  + seg * 4);
            float4 y = *(const float4*)(g_y  + (size_t)n * 128 + seg * 4);
            v.x = fmaf(2.f, y.x, r.x);
            v.y = fmaf(2.f, y.y, r.y);
            v.z = fmaf(2.f, y.z, r.z);
            v.w = fmaf(2.f, y.w, r.w);
        } else {
            v = *(const float4*)(g_y + (size_t)n * 128 + seg * 4);
        }
        *(float4*)(As + row * 132 + seg * 4) = v;
    }
    cp_wait<0>();
    __syncthreads();

    const int warp = tid >> 5;
    const int mw = warp >> 1, nw = warp & 1;

    wmma::fragment<wmma::accumulator, 16, 16, 8, float> c[4];
    #pragma unroll
    for (int f = 0; f < 4; f++) wmma::fill_fragment(c[f], 0.f);

    #pragma unroll
    for (int kk = 0; kk < 16; kk++) {
        wmma::fragment<wmma::matrix_a, 16, 16, 8, wmma::precision::tf32, wmma::row_major> a;
        wmma::load_matrix_sync(a, As + (mw * 16) * 132 + kk * 8, 132);
        #pragma unroll
        for (int f = 0; f < 4; f++) {
            wmma::fragment<wmma::matrix_b, 16, 16, 8, wmma::precision::tf32, wmma::row_major> b;
            wmma::load_matrix_sync(b, Bs + (kk * 8) * 132 + nw * 64 + f * 16, 132);
            wmma::mma_sync(c[f], a, b, c[f]);
        }
    }
    __syncthreads();

    #pragma unroll
    for (int f = 0; f < 4; f++)
        wmma::store_matrix_sync(As + (mw * 16) * 132 + nw * 64 + f * 16, c[f], 132,
                                wmma::mem_row_major);
    __syncthreads();

    #pragma unroll
    for (int i = 0; i < 8; i++) {
        int j = tid + i * 256;
        int row = j >> 5, seg = j & 31;
        int n = rowBase + row;
        if (n < NP) {
            float4 v  = *(float4*)(As + row * 132 + seg * 4);
            float4 bb = *(const float4*)(b2 + seg * 4);
            float4 xr = *(const float4*)(x + (size_t)n * 128 + seg * 4);
            v.x += bb.x + xr.x;
            v.y += bb.y + xr.y;
            v.z += bb.z + xr.z;
            v.w += bb.w + xr.w;
            *(float4*)(out + (size_t)n * 128 + seg * 4) = v;
        }
    }
}

// ---------------------------------------------------------------------------
extern "C" void kernel_launch(void* const* d_in, const int* in_sizes, int n_in,
                              void* d_out, int out_size)
{
    const float* x   = (const float*)d_in[0];
    const float* w1  = (const float*)d_in[1];
    const float* b1  = (const float*)d_in[2];
    const float* w2  = (const float*)d_in[3];
    const float* b2  = (const float*)d_in[4];
    const float* rw1 = (const float*)d_in[5];
    const float* rb1 = (const float*)d_in[6];
    const float* rw2 = (const float*)d_in[7];
    const float* rb2 = (const float*)d_in[8];
    const int*   nbr = (const int*)  d_in[9];
    float* out = (float*)d_out;

    const int SMEM_G = (64 + 128) * 132 * (int)sizeof(float);          // ~99 KB
    const int SMEM_S = (2 * 128 * 68 + 2 * 64 * 68) * (int)sizeof(float); // ~102 KB
    static bool attr_done = false;
    if (!attr_done) {
        cudaFuncSetAttribute(gemm1_kernel,    cudaFuncAttributeMaxDynamicSharedMemorySize, SMEM_G);
        cudaFuncSetAttribute(gemm2_kernel,    cudaFuncAttributeMaxDynamicSharedMemorySize, SMEM_G);
        cudaFuncSetAttribute(sconv_kernel<0>, cudaFuncAttributeMaxDynamicSharedMemorySize, SMEM_S);
        cudaFuncSetAttribute(sconv_kernel<1>, cudaFuncAttributeMaxDynamicSharedMemorySize, SMEM_S);
        attr_done = true;
    }

    const int gridG = NPAD / 64;    // 1564
    const int gridS = NPAD / 128;   // 782

    gemm1_kernel<<<gridG, 256, SMEM_G>>>(x, w1, b1);
    sconv_kernel<0><<<gridS, 256, SMEM_S>>>(nbr, rw1, rb1);
    sconv_kernel<1><<<gridS, 256, SMEM_S>>>(nbr, rw2, rb2);
    gemm2_kernel<<<gridG, 256, SMEM_G>>>(x, w2, b2, out);
}